// round 6
// baseline (speedup 1.0000x reference)
#include <cuda_runtime.h>

// x:   [N_NODES, 128] fp32 = [N_NODES, 32] float4 (rows 512B, 512B-aligned)
// src, dst: [E] int32
// out: [E] fp32
//
// 4 edges per warp; for each row the WHOLE warp issues one LDG.128
// (lane l -> float4 #l of the row = 512B contiguous = 4 sequential
// sectors in a single instruction). 8 data LDGs per warp, all
// independent (MLP=8/lane). 16 FMAs/lane, 11-shuffle combined
// reduction for 4 edges, coalesced 4-float store by lanes 0-3.

__global__ void __launch_bounds__(256) edge_dot_kernel(
    const float4* __restrict__ x,
    const int4* __restrict__ src4,
    const int4* __restrict__ dst4,
    float* __restrict__ out,
    int n_edges)
{
    const int warp_id = (blockIdx.x * blockDim.x + threadIdx.x) >> 5;
    const int lane    = threadIdx.x & 31;
    const int base    = warp_id * 4;
    if (base >= n_edges) return;

    // one broadcast int4 load each for 4 src / 4 dst indices
    const int4 s4 = __ldg(&src4[warp_id]);
    const int4 d4 = __ldg(&dst4[warp_id]);

    // 8 independent whole-row loads: each LDG.128 covers one full row
    const float4 a0 = __ldg(x + (long long)s4.x * 32 + lane);
    const float4 a1 = __ldg(x + (long long)s4.y * 32 + lane);
    const float4 a2 = __ldg(x + (long long)s4.z * 32 + lane);
    const float4 a3 = __ldg(x + (long long)s4.w * 32 + lane);
    const float4 b0 = __ldg(x + (long long)d4.x * 32 + lane);
    const float4 b1 = __ldg(x + (long long)d4.y * 32 + lane);
    const float4 b2 = __ldg(x + (long long)d4.z * 32 + lane);
    const float4 b3 = __ldg(x + (long long)d4.w * 32 + lane);

    // per-lane dot4 partial for each edge (4 independent FMA chains)
    float s0 = a0.x * b0.x;  s0 = fmaf(a0.y, b0.y, s0);
    s0 = fmaf(a0.z, b0.z, s0);  s0 = fmaf(a0.w, b0.w, s0);
    float s1 = a1.x * b1.x;  s1 = fmaf(a1.y, b1.y, s1);
    s1 = fmaf(a1.z, b1.z, s1);  s1 = fmaf(a1.w, b1.w, s1);
    float s2 = a2.x * b2.x;  s2 = fmaf(a2.y, b2.y, s2);
    s2 = fmaf(a2.z, b2.z, s2);  s2 = fmaf(a2.w, b2.w, s2);
    float s3 = a3.x * b3.x;  s3 = fmaf(a3.y, b3.y, s3);
    s3 = fmaf(a3.z, b3.z, s3);  s3 = fmaf(a3.w, b3.w, s3);

    // reduce each edge-sum within 4-lane groups (offsets 1,2)
    s0 += __shfl_xor_sync(0xffffffffu, s0, 1);
    s1 += __shfl_xor_sync(0xffffffffu, s1, 1);
    s2 += __shfl_xor_sync(0xffffffffu, s2, 1);
    s3 += __shfl_xor_sync(0xffffffffu, s3, 1);
    s0 += __shfl_xor_sync(0xffffffffu, s0, 2);
    s1 += __shfl_xor_sync(0xffffffffu, s1, 2);
    s2 += __shfl_xor_sync(0xffffffffu, s2, 2);
    s3 += __shfl_xor_sync(0xffffffffu, s3, 2);

    // lane picks edge (lane&3); combine the 8 groups (offsets 4,8,16)
    const int e = lane & 3;
    float v = (e == 0) ? s0 : (e == 1) ? s1 : (e == 2) ? s2 : s3;
    v += __shfl_xor_sync(0xffffffffu, v, 4);
    v += __shfl_xor_sync(0xffffffffu, v, 8);
    v += __shfl_xor_sync(0xffffffffu, v, 16);

    // lanes 0..3 hold totals for edges base..base+3 — coalesced store
    if (lane < 4 && base + lane < n_edges)
        out[base + lane] = v;
}

extern "C" void kernel_launch(void* const* d_in, const int* in_sizes, int n_in,
                              void* d_out, int out_size)
{
    const float4* x    = (const float4*)d_in[0];
    const int4*   src4 = (const int4*)d_in[1];
    const int4*   dst4 = (const int4*)d_in[2];
    float*        out  = (float*)d_out;

    const int n_edges = in_sizes[1];                  // E = 1,000,000 (div by 4)
    const int threads = 256;                          // 8 warps, 32 edges/block
    const int edges_per_block = (threads / 32) * 4;
    const int blocks = (n_edges + edges_per_block - 1) / edges_per_block;

    edge_dot_kernel<<<blocks, threads>>>(x, src4, dst4, out, n_edges);
}

// round 7
// speedup vs baseline: 1.1097x; 1.1097x over previous
#include <cuda_runtime.h>

// x:   [N_NODES, 128] fp32 = [N_NODES, 64] float2 (rows 512B, aligned)
// src, dst: [E] int32
// out: [E] fp32
//
// 4 edges per warp; whole warp per half-row via LDG.64:
// lane l reads float2 #l -> 32 x 8B = 256B = 2 sectors per LDG.
// 16 data LDGs per warp (2 per row), all independent.
// Balances LSU issue floor (1.82 cyc/LDG) against L1tex wavefront
// rate — both ~60K cyc/SM, below the ~110K wall of R3/R5/R6.

__global__ void __launch_bounds__(256) edge_dot_kernel(
    const float2* __restrict__ x,
    const int4* __restrict__ src4,
    const int4* __restrict__ dst4,
    float* __restrict__ out,
    int n_edges)
{
    const int warp_id = (blockIdx.x * blockDim.x + threadIdx.x) >> 5;
    const int lane    = threadIdx.x & 31;
    const int base    = warp_id * 4;
    if (base >= n_edges) return;

    // broadcast index loads: 4 src + 4 dst indices per warp
    const int4 s4 = __ldg(&src4[warp_id]);
    const int4 d4 = __ldg(&dst4[warp_id]);

    const float2* __restrict__ a0 = x + (long long)s4.x * 64 + lane;
    const float2* __restrict__ a1 = x + (long long)s4.y * 64 + lane;
    const float2* __restrict__ a2 = x + (long long)s4.z * 64 + lane;
    const float2* __restrict__ a3 = x + (long long)s4.w * 64 + lane;
    const float2* __restrict__ b0 = x + (long long)d4.x * 64 + lane;
    const float2* __restrict__ b1 = x + (long long)d4.y * 64 + lane;
    const float2* __restrict__ b2 = x + (long long)d4.z * 64 + lane;
    const float2* __restrict__ b3 = x + (long long)d4.w * 64 + lane;

    // 16 independent LDG.64, each = 2 contiguous sectors of one row
    const float2 aL0 = __ldg(a0), aH0 = __ldg(a0 + 32);
    const float2 aL1 = __ldg(a1), aH1 = __ldg(a1 + 32);
    const float2 aL2 = __ldg(a2), aH2 = __ldg(a2 + 32);
    const float2 aL3 = __ldg(a3), aH3 = __ldg(a3 + 32);
    const float2 bL0 = __ldg(b0), bH0 = __ldg(b0 + 32);
    const float2 bL1 = __ldg(b1), bH1 = __ldg(b1 + 32);
    const float2 bL2 = __ldg(b2), bH2 = __ldg(b2 + 32);
    const float2 bL3 = __ldg(b3), bH3 = __ldg(b3 + 32);

    // per-lane partial dot for each edge (4 FMAs each, independent chains)
    float s0 = aL0.x * bL0.x;  s0 = fmaf(aL0.y, bL0.y, s0);
    s0 = fmaf(aH0.x, bH0.x, s0);  s0 = fmaf(aH0.y, bH0.y, s0);
    float s1 = aL1.x * bL1.x;  s1 = fmaf(aL1.y, bL1.y, s1);
    s1 = fmaf(aH1.x, bH1.x, s1);  s1 = fmaf(aH1.y, bH1.y, s1);
    float s2 = aL2.x * bL2.x;  s2 = fmaf(aL2.y, bL2.y, s2);
    s2 = fmaf(aH2.x, bH2.x, s2);  s2 = fmaf(aH2.y, bH2.y, s2);
    float s3 = aL3.x * bL3.x;  s3 = fmaf(aL3.y, bL3.y, s3);
    s3 = fmaf(aH3.x, bH3.x, s3);  s3 = fmaf(aH3.y, bH3.y, s3);

    // reduce each edge-sum within 4-lane groups (offsets 1,2)
    s0 += __shfl_xor_sync(0xffffffffu, s0, 1);
    s1 += __shfl_xor_sync(0xffffffffu, s1, 1);
    s2 += __shfl_xor_sync(0xffffffffu, s2, 1);
    s3 += __shfl_xor_sync(0xffffffffu, s3, 1);
    s0 += __shfl_xor_sync(0xffffffffu, s0, 2);
    s1 += __shfl_xor_sync(0xffffffffu, s1, 2);
    s2 += __shfl_xor_sync(0xffffffffu, s2, 2);
    s3 += __shfl_xor_sync(0xffffffffu, s3, 2);

    // lane picks its edge (lane&3); combine the 8 groups (offsets 4,8,16)
    const int e = lane & 3;
    float v = (e == 0) ? s0 : (e == 1) ? s1 : (e == 2) ? s2 : s3;
    v += __shfl_xor_sync(0xffffffffu, v, 4);
    v += __shfl_xor_sync(0xffffffffu, v, 8);
    v += __shfl_xor_sync(0xffffffffu, v, 16);

    // lanes 0..3 hold totals for edges base..base+3 — coalesced store
    if (lane < 4 && base + lane < n_edges)
        out[base + lane] = v;
}

extern "C" void kernel_launch(void* const* d_in, const int* in_sizes, int n_in,
                              void* d_out, int out_size)
{
    const float2* x    = (const float2*)d_in[0];
    const int4*   src4 = (const int4*)d_in[1];
    const int4*   dst4 = (const int4*)d_in[2];
    float*        out  = (float*)d_out;

    const int n_edges = in_sizes[1];                  // E = 1,000,000 (div by 4)
    const int threads = 256;                          // 8 warps, 32 edges/block
    const int edges_per_block = (threads / 32) * 4;
    const int blocks = (n_edges + edges_per_block - 1) / edges_per_block;

    edge_dot_kernel<<<blocks, threads>>>(x, src4, dst4, out, n_edges);
}